// round 13
// baseline (speedup 1.0000x reference)
#include <cuda_runtime.h>
#include <cuda_bf16.h>
#include <math.h>
#include <stdint.h>

#define BB 8
#define SS 4096
#define TT (BB*SS)          // 32768 tokens
#define DD 1024
#define DKK 128
#define DVV 128
#define MM 256
#define EPSV 1e-6f

#define LDR 36              // fp32 row-major smem leading dim (floats)
#define LDT 136             // fp32 k-major smem leading dim (floats)
#define TILE_B 18432        // fp32 128x32 tile w/ pad, bytes
#define TILE_F 4608
#define BT_B 8192           // bf16 128x32 tile, swizzled, no pad

#define K1_STG (4*BT_B)     // Ah, Am, Bh, Bm = 32768
#define SMEM_K1 (2*K1_STG)  // 65536 (2 CTA/SM)
#define K2_STG (4*BT_B)
#define SMEM_K2 (2*K2_STG)  // 65536
#define STG2_B (2*TILE_B)
#define SMEM2 (2*STG2_B)    // 73728 (k4, k5)

// ---------------- scratch (device globals; no allocation allowed) -------------
__device__ __align__(128) __nv_bfloat16 g_xbh[(size_t)TT*DD];  // x hi
__device__ __align__(128) __nv_bfloat16 g_xbm[(size_t)TT*DD];  // x mid
__device__ __align__(128) __nv_bfloat16 g_Wbh[384*DD];   // Wq|Wk|Wv transposed [n][k], hi
__device__ __align__(128) __nv_bfloat16 g_Wbm[384*DD];   // mid
__device__ __align__(128) __nv_bfloat16 g_ombh[MM*DKK];
__device__ __align__(128) __nv_bfloat16 g_ombm[MM*DKK];
__device__ __align__(128) __nv_bfloat16 g_qbh[(size_t)TT*DKK];
__device__ __align__(128) __nv_bfloat16 g_qbm[(size_t)TT*DKK];
__device__ __align__(128) __nv_bfloat16 g_kbh[(size_t)TT*DKK];
__device__ __align__(128) __nv_bfloat16 g_kbm[(size_t)TT*DKK];
__device__ float g_vr[(size_t)TT*DVV];      // v, tf32-rounded
__device__ float g_pq[(size_t)TT*MM];       // logits, then phi_q (tf32-rounded)
__device__ float g_pk[(size_t)TT*MM];       // raw k logits (exp fused into k4)
__device__ float g_qn[TT];
__device__ float g_kn[TT];
__device__ float g_kvT[BB*DVV*MM];          // kv transposed [b][d][m]
__device__ float g_ksum[BB*MM];
__device__ float g_gkmax;

// ---------------- helpers -----------------------------------------------------
__device__ __forceinline__ uint32_t smem_u32(const void* p) {
    uint32_t a;
    asm("{ .reg .u64 t; cvta.to.shared.u64 t, %1; cvt.u32.u64 %0, t; }" : "=r"(a) : "l"(p));
    return a;
}
__device__ __forceinline__ float rndtf(float x) {
    uint32_t r; asm("cvt.rna.tf32.f32 %0, %1;" : "=r"(r) : "f"(x));
    return __uint_as_float(r);
}
__device__ __forceinline__ void atomicMaxFloat(float* addr, float v) {
    if (v >= 0.0f) atomicMax((int*)addr, __float_as_int(v));
    else           atomicMin((unsigned int*)addr, __float_as_uint(v));
}
__device__ __forceinline__ void cpa16(uint32_t d, const void* s) {
    asm volatile("cp.async.cg.shared.global [%0], [%1], 16;" :: "r"(d), "l"(s));
}
#define CP_COMMIT() asm volatile("cp.async.commit_group;" ::: "memory")
#define CP_WAIT0()  asm volatile("cp.async.wait_group 0;" ::: "memory")
#define CP_WAIT1()  asm volatile("cp.async.wait_group 1;" ::: "memory")

#define MMA8(d, a, b) \
    asm volatile("mma.sync.aligned.m16n8k8.row.col.f32.tf32.tf32.f32 " \
        "{%0,%1,%2,%3}, {%4,%5,%6,%7}, {%8,%9}, {%0,%1,%2,%3};" \
        : "+f"((d)[0]), "+f"((d)[1]), "+f"((d)[2]), "+f"((d)[3]) \
        : "r"((a)[0]), "r"((a)[1]), "r"((a)[2]), "r"((a)[3]), \
          "r"((b)[0]), "r"((b)[1]))

#define MMA16(d, a, b) \
    asm volatile("mma.sync.aligned.m16n8k16.row.col.f32.bf16.bf16.f32 " \
        "{%0,%1,%2,%3}, {%4,%5,%6,%7}, {%8,%9}, {%0,%1,%2,%3};" \
        : "+f"((d)[0]), "+f"((d)[1]), "+f"((d)[2]), "+f"((d)[3]) \
        : "r"((a)[0]), "r"((a)[1]), "r"((a)[2]), "r"((a)[3]), \
          "r"((b)[0]), "r"((b)[1]))

#define LDSM4(r0, r1, r2, r3, addr) \
    asm volatile("ldmatrix.sync.aligned.m8n8.x4.shared.b16 {%0,%1,%2,%3}, [%4];" \
        : "=r"(r0), "=r"(r1), "=r"(r2), "=r"(r3) : "r"(addr))

// fp32 loaders (k4/k5)
__device__ __forceinline__ void ldR4(uint32_t sb, const float* src, int ldg, int tid) {
    #pragma unroll
    for (int t = 0; t < 4; t++) {
        int idx = tid + t*256, r = idx >> 3, c = idx & 7;
        cpa16(sb + (uint32_t)(r*LDR + c*4)*4u, src + (size_t)r*ldg + c*4);
    }
}
__device__ __forceinline__ void ldT4(uint32_t sb, const float* src, int ldg, int tid) {
    #pragma unroll
    for (int t = 0; t < 4; t++) {
        int idx = tid + t*256, r = idx >> 5, c = idx & 31;
        cpa16(sb + (uint32_t)(r*LDT + c*4)*4u, src + (size_t)r*ldg + c*4);
    }
}
// bf16 tile loader with XOR swizzle: 128 rows x 32 bf16 (64B/row), granule^=(r>>1)&3
__device__ __forceinline__ void ldBS(uint32_t sb, const __nv_bfloat16* src, int ldg, int tid) {
    #pragma unroll
    for (int t = 0; t < 2; t++) {
        int idx = tid + t*256, r = idx >> 2, c = idx & 3;
        uint32_t cs = (uint32_t)(c ^ ((r >> 1) & 3));
        cpa16(sb + (uint32_t)(r*64) + cs*16u, src + (size_t)r*ldg + c*8);
    }
}

// fp32 tf32 mma cores (k4/k5)
__device__ __forceinline__ void coreR(const float* As, const float* Bs,
                                      float acc[4][4][4], int wm, int wn, int gid, int tig) {
    #pragma unroll
    for (int k8 = 0; k8 < 32; k8 += 8) {
        uint32_t a[4][4], b[4][2];
        #pragma unroll
        for (int im = 0; im < 4; im++) {
            int rb = wm + im*16;
            a[im][0] = __float_as_uint(As[(rb+gid  )*LDR + k8+tig  ]);
            a[im][1] = __float_as_uint(As[(rb+gid+8)*LDR + k8+tig  ]);
            a[im][2] = __float_as_uint(As[(rb+gid  )*LDR + k8+tig+4]);
            a[im][3] = __float_as_uint(As[(rb+gid+8)*LDR + k8+tig+4]);
        }
        #pragma unroll
        for (int jn = 0; jn < 4; jn++) {
            int nb = wn + jn*8;
            b[jn][0] = __float_as_uint(Bs[(nb+gid)*LDR + k8+tig  ]);
            b[jn][1] = __float_as_uint(Bs[(nb+gid)*LDR + k8+tig+4]);
        }
        #pragma unroll
        for (int im = 0; im < 4; im++)
            #pragma unroll
            for (int jn = 0; jn < 4; jn++)
                MMA8(acc[im][jn], a[im], b[jn]);
    }
}
__device__ __forceinline__ void coreT(const float* As, const float* Bs,
                                      float acc[4][4][4], int wm, int wn, int gid, int tig) {
    #pragma unroll
    for (int k8 = 0; k8 < 32; k8 += 8) {
        uint32_t a[4][4], b[4][2];
        #pragma unroll
        for (int im = 0; im < 4; im++) {
            int rb = wm + im*16;
            a[im][0] = __float_as_uint(As[(k8+tig  )*LDT + rb+gid  ]);
            a[im][1] = __float_as_uint(As[(k8+tig  )*LDT + rb+gid+8]);
            a[im][2] = __float_as_uint(As[(k8+tig+4)*LDT + rb+gid  ]);
            a[im][3] = __float_as_uint(As[(k8+tig+4)*LDT + rb+gid+8]);
        }
        #pragma unroll
        for (int jn = 0; jn < 4; jn++) {
            int nb = wn + jn*8;
            b[jn][0] = __float_as_uint(Bs[(k8+tig  )*LDT + nb+gid]);
            b[jn][1] = __float_as_uint(Bs[(k8+tig+4)*LDT + nb+gid]);
        }
        #pragma unroll
        for (int im = 0; im < 4; im++)
            #pragma unroll
            for (int jn = 0; jn < 4; jn++)
                MMA8(acc[im][jn], a[im], b[jn]);
    }
}
// 64x32 warp tile, bf16 m16n8k16 via ldmatrix; swizzled LDB=32 layout
__device__ __forceinline__ void coreRB(uint32_t As, uint32_t Bs,
                                       float acc[4][4][4], int wm, int wn, int lane) {
    const int l15 = lane & 15;
    const int ahi = (lane >> 4) & 1;
    const int l7  = lane & 7;
    const int bk  = (lane >> 3) & 1;
    const int bn  = (lane >> 4) & 1;
    #pragma unroll
    for (int k16 = 0; k16 < 32; k16 += 16) {
        uint32_t a[4][4], b[4][2];
        const int gbase = k16 >> 3;
        #pragma unroll
        for (int im = 0; im < 4; im++) {
            int r = wm + im*16 + l15;
            uint32_t g = (uint32_t)((gbase + ahi) ^ ((r >> 1) & 3));
            uint32_t addr = As + (uint32_t)(r*64) + g*16u;
            LDSM4(a[im][0], a[im][1], a[im][2], a[im][3], addr);
        }
        #pragma unroll
        for (int jp = 0; jp < 2; jp++) {
            int r = wn + jp*16 + bn*8 + l7;
            uint32_t g = (uint32_t)((gbase + bk) ^ ((r >> 1) & 3));
            uint32_t addr = Bs + (uint32_t)(r*64) + g*16u;
            uint32_t r0, r1, r2, r3;
            LDSM4(r0, r1, r2, r3, addr);
            b[jp*2  ][0] = r0; b[jp*2  ][1] = r1;
            b[jp*2+1][0] = r2; b[jp*2+1][1] = r3;
        }
        #pragma unroll
        for (int im = 0; im < 4; im++)
            #pragma unroll
            for (int jn = 0; jn < 4; jn++)
                MMA16(acc[im][jn], a[im], b[jn]);
    }
}

// ---------------- prep kernels ------------------------------------------------
__global__ __launch_bounds__(256) void k_prep_w(
    const float* __restrict__ Wq, const float* __restrict__ Wk, const float* __restrict__ Wv) {
    int idx = blockIdx.x * 256 + threadIdx.x;          // 0..393215
    int row = idx >> 10, k = idx & 1023;
    const float* W = (row < 128) ? Wq : (row < 256) ? Wk : Wv;
    int n = row & 127;
    float v = W[(size_t)k * DKK + n];
    __nv_bfloat16 h = __float2bfloat16_rn(v);
    g_Wbh[idx] = h;
    g_Wbm[idx] = __float2bfloat16_rn(v - __bfloat162float(h));
}
__global__ __launch_bounds__(256) void k_prep_om(const float* __restrict__ om) {
    int idx = blockIdx.x * 256 + threadIdx.x;          // 0..32767
    float v = om[idx];
    __nv_bfloat16 h = __float2bfloat16_rn(v);
    g_ombh[idx] = h;
    g_ombm[idx] = __float2bfloat16_rn(v - __bfloat162float(h));
}
// split x -> bf16 hi/mid (streaming)
__global__ __launch_bounds__(256) void k_prep_xb(const float* __restrict__ x) {
    size_t n4 = (size_t)TT*DD/4;
    size_t stride = (size_t)gridDim.x * 256;
    const float4* x4 = (const float4*)x;
    uint2* h4 = (uint2*)g_xbh;
    uint2* m4 = (uint2*)g_xbm;
    for (size_t i = (size_t)blockIdx.x*256 + threadIdx.x; i < n4; i += stride) {
        float4 v = x4[i];
        __nv_bfloat16 hx = __float2bfloat16_rn(v.x);
        __nv_bfloat16 hy = __float2bfloat16_rn(v.y);
        __nv_bfloat16 hz = __float2bfloat16_rn(v.z);
        __nv_bfloat16 hw = __float2bfloat16_rn(v.w);
        uint2 ho, mo;
        __nv_bfloat162 t0 = __halves2bfloat162(hx, hy);
        __nv_bfloat162 t1 = __halves2bfloat162(hz, hw);
        ho.x = *(uint32_t*)&t0; ho.y = *(uint32_t*)&t1;
        __nv_bfloat162 u0 = __halves2bfloat162(
            __float2bfloat16_rn(v.x - __bfloat162float(hx)),
            __float2bfloat16_rn(v.y - __bfloat162float(hy)));
        __nv_bfloat162 u1 = __halves2bfloat162(
            __float2bfloat16_rn(v.z - __bfloat162float(hz)),
            __float2bfloat16_rn(v.w - __bfloat162float(hw)));
        mo.x = *(uint32_t*)&u0; mo.y = *(uint32_t*)&u1;
        h4[i] = ho; m4[i] = mo;
    }
}
__global__ void k0_init() {
    int tid = blockIdx.x * blockDim.x + threadIdx.x;
    int nt  = gridDim.x * blockDim.x;
    if (tid == 0) g_gkmax = __int_as_float(0xff800000);
    for (int i = tid; i < BB*DVV*MM; i += nt) g_kvT[i] = 0.0f;
    for (int i = tid; i < BB*MM;     i += nt) g_ksum[i] = 0.0f;
}

// ---------------- K1: unified q/k/v GEMM, bf16x3, fused norms -----------------
// grid (3, 256): blockIdx.x = which (L2 reuse of x across q/k/v), .y = row block
__global__ __launch_bounds__(256,2) void k1_all(
    const float* __restrict__ bq, const float* __restrict__ bk, const float* __restrict__ bv) {
    extern __shared__ char smarr[];
    __shared__ float snrm[128];
    uint32_t sb = smem_u32(smarr);
    const int tid = threadIdx.x, lane = tid & 31, wid = tid >> 5;
    const int gid = lane >> 2, tig = lane & 3;
    const int wm = (wid >> 2)*64, wn = (wid & 3)*32;
    const int which = blockIdx.x;
    const int row0 = blockIdx.y * 128;
    const __nv_bfloat16* Xh = g_xbh + (size_t)row0*DD;
    const __nv_bfloat16* Xm = g_xbm + (size_t)row0*DD;
    const __nv_bfloat16* Wh = g_Wbh + (size_t)which*128*DD;
    const __nv_bfloat16* Wm = g_Wbm + (size_t)which*128*DD;
    float acc[4][4][4] = {};

    if (tid < 128) snrm[tid] = 0.0f;

    {
        ldBS(sb,          Xh, DD, tid);
        ldBS(sb +   BT_B, Xm, DD, tid);
        ldBS(sb + 2*BT_B, Wh, DD, tid);
        ldBS(sb + 3*BT_B, Wm, DD, tid);
        CP_COMMIT();
    }
    for (int c = 0; c < 32; c++) {
        CP_WAIT0();
        __syncthreads();
        if (c+1 < 32) {
            uint32_t st = sb + ((c+1)&1)*K1_STG;
            const int o = (c+1)*32;
            ldBS(st,          Xh + o, DD, tid);
            ldBS(st +   BT_B, Xm + o, DD, tid);
            ldBS(st + 2*BT_B, Wh + o, DD, tid);
            ldBS(st + 3*BT_B, Wm + o, DD, tid);
            CP_COMMIT();
        }
        const uint32_t S = sb + (c&1)*K1_STG;
        coreRB(S,        S + 2*BT_B, acc, wm, wn, lane);   // Ah*Bh
        coreRB(S,        S + 3*BT_B, acc, wm, wn, lane);   // Ah*Bm
        coreRB(S + BT_B, S + 2*BT_B, acc, wm, wn, lane);   // Am*Bh
    }
    if (which < 2) {
        const float QKS = 0.29730177875068026f;   // 128^-0.25
        const float* bias  = which ? bk : bq;
        __nv_bfloat16* oh = which ? g_kbh : g_qbh;
        __nv_bfloat16* om = which ? g_kbm : g_qbm;
        #pragma unroll
        for (int im = 0; im < 4; im++) {
            #pragma unroll
            for (int half = 0; half < 2; half++) {
                int row = row0 + wm + im*16 + gid + half*8;
                float rs = 0.0f;
                #pragma unroll
                for (int jn = 0; jn < 4; jn++) {
                    int col = wn + jn*8 + tig*2;
                    float f0 = (acc[im][jn][half*2+0] + bias[col])*QKS;
                    float f1 = (acc[im][jn][half*2+1] + bias[col+1])*QKS;
                    rs += f0*f0 + f1*f1;
                    size_t off = (size_t)row*128 + col;
                    __nv_bfloat16 h0 = __float2bfloat16_rn(f0);
                    __nv_bfloat16 h1 = __float2bfloat16_rn(f1);
                    *(__nv_bfloat162*)(oh + off) = __halves2bfloat162(h0, h1);
                    __nv_bfloat16 m0 = __float2bfloat16_rn(f0 - __bfloat162float(h0));
                    __nv_bfloat16 m1 = __float2bfloat16_rn(f1 - __bfloat162float(h1));
                    *(__nv_bfloat162*)(om + off) = __halves2bfloat162(m0, m1);
                }
                atomicAdd(&snrm[row - row0], rs);
            }
        }
        __syncthreads();
        if (tid < 128) (which ? g_kn : g_qn)[row0 + tid] = snrm[tid];
    } else {
        #pragma unroll
        for (int im = 0; im < 4; im++) {
            #pragma unroll
            for (int jn = 0; jn < 4; jn++) {
                int row = row0 + wm + im*16 + gid;
                int col = wn + jn*8 + tig*2;
                float b0 = bv[col], b1 = bv[col+1];
                float2 v;
                v.x = rndtf(acc[im][jn][0] + b0); v.y = rndtf(acc[im][jn][1] + b1);
                *(float2*)(g_vr + (size_t)row*128 + col) = v;
                v.x = rndtf(acc[im][jn][2] + b0); v.y = rndtf(acc[im][jn][3] + b1);
                *(float2*)(g_vr + (size_t)(row+8)*128 + col) = v;
            }
        }
    }
}

// ---------------- K2: feature projection, bf16x3 + ldmatrix -------------------
// grid (2, 2, 256): .x = mh, .y = isK, .z = row block (L2 reuse of A across mh)
__global__ __launch_bounds__(256,2) void k2_mma() {
    extern __shared__ char smarr[];
    uint32_t sb = smem_u32(smarr);
    const int tid = threadIdx.x, lane = tid & 31, wid = tid >> 5;
    const int gid = lane >> 2, tig = lane & 3;
    const int wm = (wid >> 2)*64, wn = (wid & 3)*32;
    const int mh = blockIdx.x;
    const bool isK = blockIdx.y != 0;
    const int row0 = blockIdx.z * 128;
    const __nv_bfloat16* Ah = (isK ? g_kbh : g_qbh) + (size_t)row0*DKK;
    const __nv_bfloat16* Am = (isK ? g_kbm : g_qbm) + (size_t)row0*DKK;
    const __nv_bfloat16* Obh = g_ombh + (size_t)mh*128*DKK;
    const __nv_bfloat16* Obm = g_ombm + (size_t)mh*128*DKK;
    const float* nrm  = isK ? g_kn : g_qn;
    float* out        = isK ? g_pk : g_pq;
    float acc[4][4][4] = {};
    __shared__ float wmax[8];

    {
        ldBS(sb,          Ah, DKK, tid);
        ldBS(sb +   BT_B, Am, DKK, tid);
        ldBS(sb + 2*BT_B, Obh, DKK, tid);
        ldBS(sb + 3*BT_B, Obm, DKK, tid);
        CP_COMMIT();
    }
    for (int c = 0; c < 4; c++) {
        if (c+1 < 4) {
            uint32_t st = sb + ((c+1)&1)*K2_STG;
            const int o = (c+1)*32;
            ldBS(st,          Ah + o, DKK, tid);
            ldBS(st +   BT_B, Am + o, DKK, tid);
            ldBS(st + 2*BT_B, Obh + o, DKK, tid);
            ldBS(st + 3*BT_B, Obm + o, DKK, tid);
            CP_COMMIT();
            CP_WAIT1();
        } else {
            CP_WAIT0();
        }
        __syncthreads();
        const uint32_t S = sb + (c&1)*K2_STG;
        coreRB(S,        S + 2*BT_B, acc, wm, wn, lane);
        coreRB(S,        S + 3*BT_B, acc, wm, wn, lane);
        coreRB(S + BT_B, S + 2*BT_B, acc, wm, wn, lane);
        __syncthreads();
    }
    float lmax = __int_as_float(0xff800000);
    #pragma unroll
    for (int im = 0; im < 4; im++) {
        #pragma unroll
        for (int jn = 0; jn < 4; jn++) {
            int row = row0 + wm + im*16 + gid;
            int col = mh*128 + wn + jn*8 + tig*2;
            float hn0 = 0.5f * nrm[row], hn1 = 0.5f * nrm[row+8];
            float2 v;
            v.x = acc[im][jn][0] - hn0; v.y = acc[im][jn][1] - hn0;
            *(float2*)(out + (size_t)row*MM + col) = v;
            if (isK) lmax = fmaxf(lmax, fmaxf(v.x, v.y));
            v.x = acc[im][jn][2] - hn1; v.y = acc[im][jn][3] - hn1;
            *(float2*)(out + (size_t)(row+8)*MM + col) = v;
            if (isK) lmax = fmaxf(lmax, fmaxf(v.x, v.y));
        }
    }
    if (isK) {
        #pragma unroll
        for (int o = 16; o; o >>= 1) lmax = fmaxf(lmax, __shfl_xor_sync(0xffffffffu, lmax, o));
        if (lane == 0) wmax[wid] = lmax;
        __syncthreads();
        if (tid == 0) {
            float bm = wmax[0];
            #pragma unroll
            for (int w = 1; w < 8; w++) bm = fmaxf(bm, wmax[w]);
            atomicMaxFloat(&g_gkmax, bm);
        }
    }
}

// ---------------- K3a: phi_q = rnd(exp(pq - rowmax)/16) -----------------------
__global__ __launch_bounds__(256) void k3a() {
    int t = blockIdx.x * 8 + (threadIdx.x >> 5);
    int lane = threadIdx.x & 31;
    float* pq = g_pq + (size_t)t*MM;
    float4 v0 = *(float4*)(pq + lane*4);
    float4 v1 = *(float4*)(pq + 128 + lane*4);
    float mx = fmaxf(fmaxf(fmaxf(v0.x, v0.y), fmaxf(v0.z, v0.w)),
                     fmaxf(fmaxf(v1.x, v1.y), fmaxf(v1.z, v1.w)));
    #pragma unroll
    for (int o = 16; o; o >>= 1) mx = fmaxf(mx, __shfl_xor_sync(0xffffffffu, mx, o));
    float4 e0, e1;
    e0.x = rndtf(expf(v0.x - mx)*0.0625f); e0.y = rndtf(expf(v0.y - mx)*0.0625f);
    e0.z = rndtf(expf(v0.z - mx)*0.0625f); e0.w = rndtf(expf(v0.w - mx)*0.0625f);
    e1.x = rndtf(expf(v1.x - mx)*0.0625f); e1.y = rndtf(expf(v1.y - mx)*0.0625f);
    e1.z = rndtf(expf(v1.z - mx)*0.0625f); e1.w = rndtf(expf(v1.w - mx)*0.0625f);
    *(float4*)(pq + lane*4) = e0;
    *(float4*)(pq + 128 + lane*4) = e1;
}

// ---------------- K4: kvT += phi_k^T v  (fused exp + ksum) --------------------
__global__ __launch_bounds__(256,2) void k4_mma() {
    extern __shared__ char smarr[];
    uint32_t sb = smem_u32(smarr);
    const int tid = threadIdx.x, lane = tid & 31, wid = tid >> 5;
    const int gid = lane >> 2, tig = lane & 3;
    const int wm = (wid >> 2)*64, wn = (wid & 3)*32;
    const int b = blockIdx.x, m0 = blockIdx.y * 128, sp = blockIdx.z;
    const float gm = g_gkmax;
    const float* Asrc = g_pk + ((size_t)b*SS + sp*512)*MM + m0;   // raw logits
    const float* Bsrc = g_vr + ((size_t)b*SS + sp*512)*DVV;
    float acc[4][4][4] = {};
    float ks = 0.0f;
    const int km = tid & 127, kh = tid >> 7;

    { ldT4(sb, Asrc, MM, tid); ldT4(sb + TILE_B, Bsrc, DVV, tid); CP_COMMIT(); }
    for (int c = 0; c < 16; c++) {
        if (c+1 < 16) {
            uint32_t st = sb + ((c+1)&1)*STG2_B;
            ldT4(st, Asrc + (size_t)(c+1)*32*MM, MM, tid);
            ldT4(st + TILE_B, Bsrc + (size_t)(c+1)*32*DVV, DVV, tid);
            CP_COMMIT();
            CP_WAIT1();
        } else {
            CP_WAIT0();
        }
        __syncthreads();
        float* S = (float*)(smarr + (c&1)*STG2_B);
        // fused k3b: phi_k = rnd(exp(logit - gmax)/16), in place on the A tile
        #pragma unroll
        for (int i = 0; i < 16; i++) {
            int idx = tid + i*256, r = idx >> 7, m = idx & 127;
            float v = S[r*LDT + m];
            S[r*LDT + m] = rndtf(expf(v - gm)*0.0625f);
        }
        __syncthreads();
        coreT(S, S + TILE_F, acc, wm, wn, gid, tig);
        // fused ksum: column sums of the phi_k tile
        #pragma unroll
        for (int s = 0; s < 16; s++) ks += S[(kh*16 + s)*LDT + km];
        __syncthreads();
    }
    float* kvb = g_kvT + (size_t)b*DVV*MM;
    #pragma unroll
    for (int im = 0; im < 4; im++) {
        #pragma unroll
        for (int jn = 0; jn < 4; jn++) {
            int m = m0 + wm + im*16 + gid;
            int d = wn + jn*8 + tig*2;
            atomicAdd(&kvb[(size_t)d*MM + m],       acc[im][jn][0]);
            atomicAdd(&kvb[(size_t)(d+1)*MM + m],   acc[im][jn][1]);
            atomicAdd(&kvb[(size_t)d*MM + m+8],     acc[im][jn][2]);
            atomicAdd(&kvb[(size_t)(d+1)*MM + m+8], acc[im][jn][3]);
        }
    }
    atomicAdd(&g_ksum[b*MM + m0 + km], ks);
}

// ---------------- K4c: round kvT in place -------------------------------------
__global__ __launch_bounds__(256) void k4c_round() {
    int i = blockIdx.x * 256 + threadIdx.x;
    int n = BB*DVV*MM;
    for (; i < n; i += gridDim.x * 256) g_kvT[i] = rndtf(g_kvT[i]);
}

// ---------------- K5: out = (phi_q @ kv) / den  (fused den) -------------------
__global__ __launch_bounds__(256,2) void k5_mma(float* __restrict__ out) {
    extern __shared__ char smarr[];
    __shared__ float ksm[MM];
    __shared__ float sden[128];
    uint32_t sb = smem_u32(smarr);
    const int tid = threadIdx.x, lane = tid & 31, wid = tid >> 5;
    const int gid = lane >> 2, tig = lane & 3;
    const int wm = (wid >> 2)*64, wn = (wid & 3)*32;
    const int row0 = blockIdx.x * 128;
    const int b = blockIdx.x >> 5;
    const float* Asrc = g_pq + (size_t)row0*MM;
    const float* Bsrc = g_kvT + (size_t)b*DVV*MM;
    float acc[4][4][4] = {};
    const int dr = tid >> 1, dh = tid & 1;   // den accumulation mapping

    ksm[tid] = g_ksum[b*MM + tid];
    if (tid < 128) sden[tid] = 0.0f;

    { ldR4(sb, Asrc, MM, tid); ldR4(sb + TILE_B, Bsrc, MM, tid); CP_COMMIT(); }
    for (int c = 0; c < 8; c++) {
        if (c+1 < 8) {
            uint32_t st = sb + ((c+1)&1)*STG2_B;
            ldR4(st, Asrc + (c+1)*32, MM, tid);
            ldR4(st + TILE_B, Bsrc + (c+1)*32, MM, tid);
            CP_COMMIT();
            CP_WAIT1();
        } else {
            CP_WAIT0();
        }
        __syncthreads();
        const float* S = (const float*)(smarr + (c&1)*STG2_B);
        // fused den: partial dot of phi_q rows with ksum chunk
        {
            float s = 0.0f;
            #pragma unroll
            for (int j = 0; j < 16; j++)
                s += S[dr*LDR + dh*16 + j] * ksm[c*32 + dh*16 + j];
            atomicAdd(&sden[dr], s);
        }
        coreR(S, S + TILE_F, acc, wm, wn, gid, tig);
        __syncthreads();
    }
    #pragma unroll
    for (int im = 0; im < 4; im++) {
        #pragma unroll
        for (int jn = 0; jn < 4; jn++) {
            int lrow = wm + im*16 + gid;
            int row = row0 + lrow;
            int col = wn + jn*8 + tig*2;
            float inv0 = 1.0f / (sden[lrow]     + EPSV);
            float inv1 = 1.0f / (sden[lrow + 8] + EPSV);
            float2 v;
            v.x = acc[im][jn][0]*inv0; v.y = acc[im][jn][1]*inv0;
            *(float2*)(out + (size_t)row*DVV + col) = v;
            v.x = acc[im][jn][2]*inv1; v.y = acc[im][jn][3]*inv1;
            *(float2*)(out + (size_t)(row+8)*DVV + col) = v;
        }
    }
}

// ---------------- launch ------------------------------------------------------
extern "C" void kernel_launch(void* const* d_in, const int* in_sizes, int n_in,
                              void* d_out, int out_size) {
    const float* x     = (const float*)d_in[0];
    const float* Wq    = (const float*)d_in[1];
    const float* bq    = (const float*)d_in[2];
    const float* Wk    = (const float*)d_in[3];
    const float* bk    = (const float*)d_in[4];
    const float* Wv    = (const float*)d_in[5];
    const float* bv    = (const float*)d_in[6];
    const float* omega = (const float*)d_in[7];
    float* out = (float*)d_out;

    cudaFuncSetAttribute(k1_all, cudaFuncAttributeMaxDynamicSharedMemorySize, SMEM_K1);
    cudaFuncSetAttribute(k2_mma, cudaFuncAttributeMaxDynamicSharedMemorySize, SMEM_K2);
    cudaFuncSetAttribute(k4_mma, cudaFuncAttributeMaxDynamicSharedMemorySize, SMEM2);
    cudaFuncSetAttribute(k5_mma, cudaFuncAttributeMaxDynamicSharedMemorySize, SMEM2);

    k_prep_w<<<1536, 256>>>(Wq, Wk, Wv);
    k_prep_om<<<128, 256>>>(omega);
    k_prep_xb<<<4096, 256>>>(x);
    k0_init<<<64, 256>>>();
    k1_all<<<dim3(3, 256), 256, SMEM_K1>>>(bq, bk, bv);
    k2_mma<<<dim3(2, 2, 256), 256, SMEM_K2>>>();
    k3a<<<TT/8, 256>>>();
    k4_mma<<<dim3(8, 2, 8), 256, SMEM2>>>();
    k4c_round<<<256, 256>>>();
    k5_mma<<<256, 256, SMEM2>>>(out);
}

// round 14
// speedup vs baseline: 1.0665x; 1.0665x over previous
#include <cuda_runtime.h>
#include <cuda_bf16.h>
#include <math.h>
#include <stdint.h>

#define BB 8
#define SS 4096
#define TT (BB*SS)          // 32768 tokens
#define DD 1024
#define DKK 128
#define DVV 128
#define MM 256
#define EPSV 1e-6f

#define LDR 36              // fp32 row-major smem leading dim (floats)
#define LDT 136             // fp32 k-major smem leading dim (floats)
#define TILE_B 18432        // fp32 128x32 tile w/ pad, bytes
#define TILE_F 4608
#define BT_B 8192           // bf16 128x32 tile, swizzled, no pad

#define K1X_STG (TILE_B + 2*BT_B)        // Xraw + Bh + Bm = 34816
#define SMEM_K1 (2*K1X_STG + 2*BT_B)     // + Ah, Am = 86016 (2 CTA/SM)
#define K2_STG (4*BT_B)
#define SMEM_K2 (2*K2_STG)  // 65536
#define STG2_B (2*TILE_B)
#define SMEM2 (2*STG2_B)    // 73728 (k4, k5)

// ---------------- scratch (device globals; no allocation allowed) -------------
__device__ __align__(128) __nv_bfloat16 g_Wbh[384*DD];   // Wq|Wk|Wv transposed [n][k], hi
__device__ __align__(128) __nv_bfloat16 g_Wbm[384*DD];   // mid
__device__ __align__(128) __nv_bfloat16 g_ombh[MM*DKK];
__device__ __align__(128) __nv_bfloat16 g_ombm[MM*DKK];
__device__ __align__(128) __nv_bfloat16 g_qbh[(size_t)TT*DKK];
__device__ __align__(128) __nv_bfloat16 g_qbm[(size_t)TT*DKK];
__device__ __align__(128) __nv_bfloat16 g_kbh[(size_t)TT*DKK];
__device__ __align__(128) __nv_bfloat16 g_kbm[(size_t)TT*DKK];
__device__ float g_vr[(size_t)TT*DVV];      // v, tf32-rounded
__device__ float g_pq[(size_t)TT*MM];       // logits, then phi_q (tf32-rounded)
__device__ float g_pk[(size_t)TT*MM];       // logits, then phi_k (tf32-rounded)
__device__ float g_qn[TT];
__device__ float g_kn[TT];
__device__ float g_kvT[BB*DVV*MM];          // kv transposed [b][d][m]
__device__ float g_ksum[BB*MM];
__device__ float g_gkmax;

// ---------------- helpers -----------------------------------------------------
__device__ __forceinline__ uint32_t smem_u32(const void* p) {
    uint32_t a;
    asm("{ .reg .u64 t; cvta.to.shared.u64 t, %1; cvt.u32.u64 %0, t; }" : "=r"(a) : "l"(p));
    return a;
}
__device__ __forceinline__ float rndtf(float x) {
    uint32_t r; asm("cvt.rna.tf32.f32 %0, %1;" : "=r"(r) : "f"(x));
    return __uint_as_float(r);
}
__device__ __forceinline__ void atomicMaxFloat(float* addr, float v) {
    if (v >= 0.0f) atomicMax((int*)addr, __float_as_int(v));
    else           atomicMin((unsigned int*)addr, __float_as_uint(v));
}
__device__ __forceinline__ void cpa16(uint32_t d, const void* s) {
    asm volatile("cp.async.cg.shared.global [%0], [%1], 16;" :: "r"(d), "l"(s));
}
#define CP_COMMIT() asm volatile("cp.async.commit_group;" ::: "memory")
#define CP_WAIT0()  asm volatile("cp.async.wait_group 0;" ::: "memory")
#define CP_WAIT1()  asm volatile("cp.async.wait_group 1;" ::: "memory")

#define MMA8(d, a, b) \
    asm volatile("mma.sync.aligned.m16n8k8.row.col.f32.tf32.tf32.f32 " \
        "{%0,%1,%2,%3}, {%4,%5,%6,%7}, {%8,%9}, {%0,%1,%2,%3};" \
        : "+f"((d)[0]), "+f"((d)[1]), "+f"((d)[2]), "+f"((d)[3]) \
        : "r"((a)[0]), "r"((a)[1]), "r"((a)[2]), "r"((a)[3]), \
          "r"((b)[0]), "r"((b)[1]))

#define MMA16(d, a, b) \
    asm volatile("mma.sync.aligned.m16n8k16.row.col.f32.bf16.bf16.f32 " \
        "{%0,%1,%2,%3}, {%4,%5,%6,%7}, {%8,%9}, {%0,%1,%2,%3};" \
        : "+f"((d)[0]), "+f"((d)[1]), "+f"((d)[2]), "+f"((d)[3]) \
        : "r"((a)[0]), "r"((a)[1]), "r"((a)[2]), "r"((a)[3]), \
          "r"((b)[0]), "r"((b)[1]))

#define LDSM4(r0, r1, r2, r3, addr) \
    asm volatile("ldmatrix.sync.aligned.m8n8.x4.shared.b16 {%0,%1,%2,%3}, [%4];" \
        : "=r"(r0), "=r"(r1), "=r"(r2), "=r"(r3) : "r"(addr))

// fp32 loaders
__device__ __forceinline__ void ldR4(uint32_t sb, const float* src, int ldg, int tid) {
    #pragma unroll
    for (int t = 0; t < 4; t++) {
        int idx = tid + t*256, r = idx >> 3, c = idx & 7;
        cpa16(sb + (uint32_t)(r*LDR + c*4)*4u, src + (size_t)r*ldg + c*4);
    }
}
__device__ __forceinline__ void ldT4(uint32_t sb, const float* src, int ldg, int tid) {
    #pragma unroll
    for (int t = 0; t < 4; t++) {
        int idx = tid + t*256, r = idx >> 5, c = idx & 31;
        cpa16(sb + (uint32_t)(r*LDT + c*4)*4u, src + (size_t)r*ldg + c*4);
    }
}
// bf16 tile loader with XOR swizzle: 128 rows x 32 bf16 (64B/row), granule^=(r>>1)&3
__device__ __forceinline__ void ldBS(uint32_t sb, const __nv_bfloat16* src, int ldg, int tid) {
    #pragma unroll
    for (int t = 0; t < 2; t++) {
        int idx = tid + t*256, r = idx >> 2, c = idx & 3;
        uint32_t cs = (uint32_t)(c ^ ((r >> 1) & 3));
        cpa16(sb + (uint32_t)(r*64) + cs*16u, src + (size_t)r*ldg + c*8);
    }
}

// fp32 tf32 mma cores (k4/k5)
__device__ __forceinline__ void coreR(const float* As, const float* Bs,
                                      float acc[4][4][4], int wm, int wn, int gid, int tig) {
    #pragma unroll
    for (int k8 = 0; k8 < 32; k8 += 8) {
        uint32_t a[4][4], b[4][2];
        #pragma unroll
        for (int im = 0; im < 4; im++) {
            int rb = wm + im*16;
            a[im][0] = __float_as_uint(As[(rb+gid  )*LDR + k8+tig  ]);
            a[im][1] = __float_as_uint(As[(rb+gid+8)*LDR + k8+tig  ]);
            a[im][2] = __float_as_uint(As[(rb+gid  )*LDR + k8+tig+4]);
            a[im][3] = __float_as_uint(As[(rb+gid+8)*LDR + k8+tig+4]);
        }
        #pragma unroll
        for (int jn = 0; jn < 4; jn++) {
            int nb = wn + jn*8;
            b[jn][0] = __float_as_uint(Bs[(nb+gid)*LDR + k8+tig  ]);
            b[jn][1] = __float_as_uint(Bs[(nb+gid)*LDR + k8+tig+4]);
        }
        #pragma unroll
        for (int im = 0; im < 4; im++)
            #pragma unroll
            for (int jn = 0; jn < 4; jn++)
                MMA8(acc[im][jn], a[im], b[jn]);
    }
}
__device__ __forceinline__ void coreT(const float* As, const float* Bs,
                                      float acc[4][4][4], int wm, int wn, int gid, int tig) {
    #pragma unroll
    for (int k8 = 0; k8 < 32; k8 += 8) {
        uint32_t a[4][4], b[4][2];
        #pragma unroll
        for (int im = 0; im < 4; im++) {
            int rb = wm + im*16;
            a[im][0] = __float_as_uint(As[(k8+tig  )*LDT + rb+gid  ]);
            a[im][1] = __float_as_uint(As[(k8+tig  )*LDT + rb+gid+8]);
            a[im][2] = __float_as_uint(As[(k8+tig+4)*LDT + rb+gid  ]);
            a[im][3] = __float_as_uint(As[(k8+tig+4)*LDT + rb+gid+8]);
        }
        #pragma unroll
        for (int jn = 0; jn < 4; jn++) {
            int nb = wn + jn*8;
            b[jn][0] = __float_as_uint(Bs[(k8+tig  )*LDT + nb+gid]);
            b[jn][1] = __float_as_uint(Bs[(k8+tig+4)*LDT + nb+gid]);
        }
        #pragma unroll
        for (int im = 0; im < 4; im++)
            #pragma unroll
            for (int jn = 0; jn < 4; jn++)
                MMA8(acc[im][jn], a[im], b[jn]);
    }
}
// 64x32 warp tile, bf16 m16n8k16 via ldmatrix; swizzled LDB=32 layout
__device__ __forceinline__ void coreRB(uint32_t As, uint32_t Bs,
                                       float acc[4][4][4], int wm, int wn, int lane) {
    const int l15 = lane & 15;
    const int ahi = (lane >> 4) & 1;
    const int l7  = lane & 7;
    const int bk  = (lane >> 3) & 1;
    const int bn  = (lane >> 4) & 1;
    #pragma unroll
    for (int k16 = 0; k16 < 32; k16 += 16) {
        uint32_t a[4][4], b[4][2];
        const int gbase = k16 >> 3;
        #pragma unroll
        for (int im = 0; im < 4; im++) {
            int r = wm + im*16 + l15;
            uint32_t g = (uint32_t)((gbase + ahi) ^ ((r >> 1) & 3));
            uint32_t addr = As + (uint32_t)(r*64) + g*16u;
            LDSM4(a[im][0], a[im][1], a[im][2], a[im][3], addr);
        }
        #pragma unroll
        for (int jp = 0; jp < 2; jp++) {
            int r = wn + jp*16 + bn*8 + l7;
            uint32_t g = (uint32_t)((gbase + bk) ^ ((r >> 1) & 3));
            uint32_t addr = Bs + (uint32_t)(r*64) + g*16u;
            uint32_t r0, r1, r2, r3;
            LDSM4(r0, r1, r2, r3, addr);
            b[jp*2  ][0] = r0; b[jp*2  ][1] = r1;
            b[jp*2+1][0] = r2; b[jp*2+1][1] = r3;
        }
        #pragma unroll
        for (int im = 0; im < 4; im++)
            #pragma unroll
            for (int jn = 0; jn < 4; jn++)
                MMA16(acc[im][jn], a[im], b[jn]);
    }
}

// split raw fp32 tile (layout R) -> bf16 hi/mid tiles (swizzled LDB=32 layout)
__device__ __forceinline__ void split_bfsw(const float* Xr, char* Ahp, char* Amp, int tid) {
    const int r = tid >> 1, c0 = (tid & 1) * 16;
    const uint32_t rb = (uint32_t)(r * 64);
    const uint32_t sw = (uint32_t)((r >> 1) & 3);
    #pragma unroll
    for (int j = 0; j < 4; j++) {
        int c = c0 + j*4;
        float4 v = *(const float4*)&Xr[r*LDR + c];
        uint32_t g = ((uint32_t)(c >> 3)) ^ sw;
        uint32_t off = rb + g*16u + (uint32_t)(c & 7)*2u;
        __nv_bfloat16 hx = __float2bfloat16_rn(v.x);
        __nv_bfloat16 hy = __float2bfloat16_rn(v.y);
        __nv_bfloat16 hz = __float2bfloat16_rn(v.z);
        __nv_bfloat16 hw = __float2bfloat16_rn(v.w);
        __nv_bfloat162 h01 = __halves2bfloat162(hx, hy);
        __nv_bfloat162 h23 = __halves2bfloat162(hz, hw);
        uint2 ho; ho.x = *(uint32_t*)&h01; ho.y = *(uint32_t*)&h23;
        *(uint2*)(Ahp + off) = ho;
        __nv_bfloat162 m01 = __halves2bfloat162(
            __float2bfloat16_rn(v.x - __bfloat162float(hx)),
            __float2bfloat16_rn(v.y - __bfloat162float(hy)));
        __nv_bfloat162 m23 = __halves2bfloat162(
            __float2bfloat16_rn(v.z - __bfloat162float(hz)),
            __float2bfloat16_rn(v.w - __bfloat162float(hw)));
        uint2 mo; mo.x = *(uint32_t*)&m01; mo.y = *(uint32_t*)&m23;
        *(uint2*)(Amp + off) = mo;
    }
}

// ---------------- prep kernels ------------------------------------------------
__global__ __launch_bounds__(256) void k_prep_w(
    const float* __restrict__ Wq, const float* __restrict__ Wk, const float* __restrict__ Wv) {
    int idx = blockIdx.x * 256 + threadIdx.x;          // 0..393215
    int row = idx >> 10, k = idx & 1023;
    const float* W = (row < 128) ? Wq : (row < 256) ? Wk : Wv;
    int n = row & 127;
    float v = W[(size_t)k * DKK + n];
    __nv_bfloat16 h = __float2bfloat16_rn(v);
    g_Wbh[idx] = h;
    g_Wbm[idx] = __float2bfloat16_rn(v - __bfloat162float(h));
}
__global__ __launch_bounds__(256) void k_prep_om(const float* __restrict__ om) {
    int idx = blockIdx.x * 256 + threadIdx.x;          // 0..32767
    float v = om[idx];
    __nv_bfloat16 h = __float2bfloat16_rn(v);
    g_ombh[idx] = h;
    g_ombm[idx] = __float2bfloat16_rn(v - __bfloat162float(h));
}
__global__ void k0_init() {
    int tid = blockIdx.x * blockDim.x + threadIdx.x;
    int nt  = gridDim.x * blockDim.x;
    if (tid == 0) g_gkmax = __int_as_float(0xff800000);
    for (int i = tid; i < BB*DVV*MM; i += nt) g_kvT[i] = 0.0f;
    for (int i = tid; i < BB*MM;     i += nt) g_ksum[i] = 0.0f;
}

// ---------------- K1: unified q/k/v GEMM, bf16x3, in-smem x split -------------
// grid (3, 256): blockIdx.x = which (L2 reuse of x across q/k/v), .y = row block
__global__ __launch_bounds__(256,2) void k1_all(
    const float* __restrict__ x,
    const float* __restrict__ bq, const float* __restrict__ bk, const float* __restrict__ bv) {
    extern __shared__ char smarr[];
    __shared__ float snrm[128];
    uint32_t sb = smem_u32(smarr);
    const int tid = threadIdx.x, lane = tid & 31, wid = tid >> 5;
    const int gid = lane >> 2, tig = lane & 3;
    const int wm = (wid >> 2)*64, wn = (wid & 3)*32;
    const int which = blockIdx.x;
    const int row0 = blockIdx.y * 128;
    const float* X = x + (size_t)row0*DD;
    const __nv_bfloat16* Wh = g_Wbh + (size_t)which*128*DD;
    const __nv_bfloat16* Wm = g_Wbm + (size_t)which*128*DD;
    const uint32_t Ah_a = sb + 2*K1X_STG;
    const uint32_t Am_a = Ah_a + BT_B;
    char* Ahp = smarr + 2*K1X_STG;
    char* Amp = Ahp + BT_B;
    float acc[4][4][4] = {};

    if (tid < 128) snrm[tid] = 0.0f;

    {   // prologue: stage 0 = Xraw(fp32), Bh, Bm
        ldR4(sb, X, DD, tid);
        ldBS(sb + TILE_B,        Wh, DD, tid);
        ldBS(sb + TILE_B + BT_B, Wm, DD, tid);
        CP_COMMIT();
    }
    for (int c = 0; c < 32; c++) {
        CP_WAIT0();
        __syncthreads();                       // stage(c) ready; compute(c-1) done
        if (c+1 < 32) {
            uint32_t st = sb + ((c+1)&1)*K1X_STG;
            const int o = (c+1)*32;
            ldR4(st, X + o, DD, tid);
            ldBS(st + TILE_B,        Wh + o, DD, tid);
            ldBS(st + TILE_B + BT_B, Wm + o, DD, tid);
            CP_COMMIT();
        }
        const uint32_t S = sb + (c&1)*K1X_STG;
        split_bfsw((const float*)(smarr + (c&1)*K1X_STG), Ahp, Amp, tid);
        __syncthreads();                       // Ah/Am ready
        coreRB(Ah_a, S + TILE_B,        acc, wm, wn, lane);   // Ah*Bh
        coreRB(Ah_a, S + TILE_B + BT_B, acc, wm, wn, lane);   // Ah*Bm
        coreRB(Am_a, S + TILE_B,        acc, wm, wn, lane);   // Am*Bh
    }
    if (which < 2) {
        const float QKS = 0.29730177875068026f;   // 128^-0.25
        const float* bias  = which ? bk : bq;
        __nv_bfloat16* oh = which ? g_kbh : g_qbh;
        __nv_bfloat16* om = which ? g_kbm : g_qbm;
        #pragma unroll
        for (int im = 0; im < 4; im++) {
            #pragma unroll
            for (int half = 0; half < 2; half++) {
                int row = row0 + wm + im*16 + gid + half*8;
                float rs = 0.0f;
                #pragma unroll
                for (int jn = 0; jn < 4; jn++) {
                    int col = wn + jn*8 + tig*2;
                    float f0 = (acc[im][jn][half*2+0] + bias[col])*QKS;
                    float f1 = (acc[im][jn][half*2+1] + bias[col+1])*QKS;
                    rs += f0*f0 + f1*f1;
                    size_t off = (size_t)row*128 + col;
                    __nv_bfloat16 h0 = __float2bfloat16_rn(f0);
                    __nv_bfloat16 h1 = __float2bfloat16_rn(f1);
                    *(__nv_bfloat162*)(oh + off) = __halves2bfloat162(h0, h1);
                    __nv_bfloat16 m0 = __float2bfloat16_rn(f0 - __bfloat162float(h0));
                    __nv_bfloat16 m1 = __float2bfloat16_rn(f1 - __bfloat162float(h1));
                    *(__nv_bfloat162*)(om + off) = __halves2bfloat162(m0, m1);
                }
                atomicAdd(&snrm[row - row0], rs);
            }
        }
        __syncthreads();
        if (tid < 128) (which ? g_kn : g_qn)[row0 + tid] = snrm[tid];
    } else {
        #pragma unroll
        for (int im = 0; im < 4; im++) {
            #pragma unroll
            for (int jn = 0; jn < 4; jn++) {
                int row = row0 + wm + im*16 + gid;
                int col = wn + jn*8 + tig*2;
                float b0 = bv[col], b1 = bv[col+1];
                float2 v;
                v.x = rndtf(acc[im][jn][0] + b0); v.y = rndtf(acc[im][jn][1] + b1);
                *(float2*)(g_vr + (size_t)row*128 + col) = v;
                v.x = rndtf(acc[im][jn][2] + b0); v.y = rndtf(acc[im][jn][3] + b1);
                *(float2*)(g_vr + (size_t)(row+8)*128 + col) = v;
            }
        }
    }
}

// ---------------- K2: feature projection, bf16x3 + ldmatrix -------------------
// grid (2, 2, 256): .x = mh, .y = isK, .z = row block
__global__ __launch_bounds__(256,2) void k2_mma() {
    extern __shared__ char smarr[];
    uint32_t sb = smem_u32(smarr);
    const int tid = threadIdx.x, lane = tid & 31, wid = tid >> 5;
    const int gid = lane >> 2, tig = lane & 3;
    const int wm = (wid >> 2)*64, wn = (wid & 3)*32;
    const int mh = blockIdx.x;
    const bool isK = blockIdx.y != 0;
    const int row0 = blockIdx.z * 128;
    const __nv_bfloat16* Ah = (isK ? g_kbh : g_qbh) + (size_t)row0*DKK;
    const __nv_bfloat16* Am = (isK ? g_kbm : g_qbm) + (size_t)row0*DKK;
    const __nv_bfloat16* Obh = g_ombh + (size_t)mh*128*DKK;
    const __nv_bfloat16* Obm = g_ombm + (size_t)mh*128*DKK;
    const float* nrm  = isK ? g_kn : g_qn;
    float* out        = isK ? g_pk : g_pq;
    float acc[4][4][4] = {};
    __shared__ float wmax[8];

    {
        ldBS(sb,          Ah, DKK, tid);
        ldBS(sb +   BT_B, Am, DKK, tid);
        ldBS(sb + 2*BT_B, Obh, DKK, tid);
        ldBS(sb + 3*BT_B, Obm, DKK, tid);
        CP_COMMIT();
    }
    for (int c = 0; c < 4; c++) {
        if (c+1 < 4) {
            uint32_t st = sb + ((c+1)&1)*K2_STG;
            const int o = (c+1)*32;
            ldBS(st,          Ah + o, DKK, tid);
            ldBS(st +   BT_B, Am + o, DKK, tid);
            ldBS(st + 2*BT_B, Obh + o, DKK, tid);
            ldBS(st + 3*BT_B, Obm + o, DKK, tid);
            CP_COMMIT();
            CP_WAIT1();
        } else {
            CP_WAIT0();
        }
        __syncthreads();
        const uint32_t S = sb + (c&1)*K2_STG;
        coreRB(S,        S + 2*BT_B, acc, wm, wn, lane);
        coreRB(S,        S + 3*BT_B, acc, wm, wn, lane);
        coreRB(S + BT_B, S + 2*BT_B, acc, wm, wn, lane);
        __syncthreads();
    }
    float lmax = __int_as_float(0xff800000);
    #pragma unroll
    for (int im = 0; im < 4; im++) {
        #pragma unroll
        for (int jn = 0; jn < 4; jn++) {
            int row = row0 + wm + im*16 + gid;
            int col = mh*128 + wn + jn*8 + tig*2;
            float hn0 = 0.5f * nrm[row], hn1 = 0.5f * nrm[row+8];
            float2 v;
            v.x = acc[im][jn][0] - hn0; v.y = acc[im][jn][1] - hn0;
            *(float2*)(out + (size_t)row*MM + col) = v;
            if (isK) lmax = fmaxf(lmax, fmaxf(v.x, v.y));
            v.x = acc[im][jn][2] - hn1; v.y = acc[im][jn][3] - hn1;
            *(float2*)(out + (size_t)(row+8)*MM + col) = v;
            if (isK) lmax = fmaxf(lmax, fmaxf(v.x, v.y));
        }
    }
    if (isK) {
        #pragma unroll
        for (int o = 16; o; o >>= 1) lmax = fmaxf(lmax, __shfl_xor_sync(0xffffffffu, lmax, o));
        if (lane == 0) wmax[wid] = lmax;
        __syncthreads();
        if (tid == 0) {
            float bm = wmax[0];
            #pragma unroll
            for (int w = 1; w < 8; w++) bm = fmaxf(bm, wmax[w]);
            atomicMaxFloat(&g_gkmax, bm);
        }
    }
}

// ---------------- K3a: phi_q = rnd(exp(pq - rowmax)/16) -----------------------
__global__ __launch_bounds__(256) void k3a() {
    int t = blockIdx.x * 8 + (threadIdx.x >> 5);
    int lane = threadIdx.x & 31;
    float* pq = g_pq + (size_t)t*MM;
    float4 v0 = *(float4*)(pq + lane*4);
    float4 v1 = *(float4*)(pq + 128 + lane*4);
    float mx = fmaxf(fmaxf(fmaxf(v0.x, v0.y), fmaxf(v0.z, v0.w)),
                     fmaxf(fmaxf(v1.x, v1.y), fmaxf(v1.z, v1.w)));
    #pragma unroll
    for (int o = 16; o; o >>= 1) mx = fmaxf(mx, __shfl_xor_sync(0xffffffffu, mx, o));
    float4 e0, e1;
    e0.x = rndtf(expf(v0.x - mx)*0.0625f); e0.y = rndtf(expf(v0.y - mx)*0.0625f);
    e0.z = rndtf(expf(v0.z - mx)*0.0625f); e0.w = rndtf(expf(v0.w - mx)*0.0625f);
    e1.x = rndtf(expf(v1.x - mx)*0.0625f); e1.y = rndtf(expf(v1.y - mx)*0.0625f);
    e1.z = rndtf(expf(v1.z - mx)*0.0625f); e1.w = rndtf(expf(v1.w - mx)*0.0625f);
    *(float4*)(pq + lane*4) = e0;
    *(float4*)(pq + 128 + lane*4) = e1;
}

// ---------------- K3b: phi_k = rnd(exp(pk - gmax)/16) -------------------------
__global__ __launch_bounds__(256) void k3b() {
    float gm = g_gkmax;
    size_t n4 = (size_t)TT*MM/4;
    size_t stride = (size_t)gridDim.x * blockDim.x;
    for (size_t i = (size_t)blockIdx.x*blockDim.x + threadIdx.x; i < n4; i += stride) {
        float4 v = ((float4*)g_pk)[i];
        v.x = rndtf(expf(v.x - gm)*0.0625f); v.y = rndtf(expf(v.y - gm)*0.0625f);
        v.z = rndtf(expf(v.z - gm)*0.0625f); v.w = rndtf(expf(v.w - gm)*0.0625f);
        ((float4*)g_pk)[i] = v;
    }
}

// ---------------- K4: kvT += phi_k^T v  (fused ksum) --------------------------
__global__ __launch_bounds__(256,2) void k4_mma() {
    extern __shared__ char smarr[];
    uint32_t sb = smem_u32(smarr);
    const int tid = threadIdx.x, lane = tid & 31, wid = tid >> 5;
    const int gid = lane >> 2, tig = lane & 3;
    const int wm = (wid >> 2)*64, wn = (wid & 3)*32;
    const int b = blockIdx.x, m0 = blockIdx.y * 128, sp = blockIdx.z;
    const float* Asrc = g_pk + ((size_t)b*SS + sp*512)*MM + m0;
    const float* Bsrc = g_vr + ((size_t)b*SS + sp*512)*DVV;
    float acc[4][4][4] = {};
    float ks = 0.0f;
    const int km = tid & 127, kh = tid >> 7;

    { ldT4(sb, Asrc, MM, tid); ldT4(sb + TILE_B, Bsrc, DVV, tid); CP_COMMIT(); }
    for (int c = 0; c < 16; c++) {
        if (c+1 < 16) {
            uint32_t st = sb + ((c+1)&1)*STG2_B;
            ldT4(st, Asrc + (size_t)(c+1)*32*MM, MM, tid);
            ldT4(st + TILE_B, Bsrc + (size_t)(c+1)*32*DVV, DVV, tid);
            CP_COMMIT();
            CP_WAIT1();
        } else {
            CP_WAIT0();
        }
        __syncthreads();
        const float* S = (const float*)(smarr + (c&1)*STG2_B);
        coreT(S, S + TILE_F, acc, wm, wn, gid, tig);
        #pragma unroll
        for (int s = 0; s < 16; s++) ks += S[(kh*16 + s)*LDT + km];
        __syncthreads();
    }
    float* kvb = g_kvT + (size_t)b*DVV*MM;
    #pragma unroll
    for (int im = 0; im < 4; im++) {
        #pragma unroll
        for (int jn = 0; jn < 4; jn++) {
            int m = m0 + wm + im*16 + gid;
            int d = wn + jn*8 + tig*2;
            atomicAdd(&kvb[(size_t)d*MM + m],       acc[im][jn][0]);
            atomicAdd(&kvb[(size_t)(d+1)*MM + m],   acc[im][jn][1]);
            atomicAdd(&kvb[(size_t)d*MM + m+8],     acc[im][jn][2]);
            atomicAdd(&kvb[(size_t)(d+1)*MM + m+8], acc[im][jn][3]);
        }
    }
    atomicAdd(&g_ksum[b*MM + m0 + km], ks);
}

// ---------------- K4c: round kvT in place -------------------------------------
__global__ __launch_bounds__(256) void k4c_round() {
    int i = blockIdx.x * 256 + threadIdx.x;
    int n = BB*DVV*MM;
    for (; i < n; i += gridDim.x * 256) g_kvT[i] = rndtf(g_kvT[i]);
}

// ---------------- K5: out = (phi_q @ kv) / den  (fused den) -------------------
__global__ __launch_bounds__(256,2) void k5_mma(float* __restrict__ out) {
    extern __shared__ char smarr[];
    __shared__ float ksm[MM];
    __shared__ float sden[128];
    uint32_t sb = smem_u32(smarr);
    const int tid = threadIdx.x, lane = tid & 31, wid = tid >> 5;
    const int gid = lane >> 2, tig = lane & 3;
    const int wm = (wid >> 2)*64, wn = (wid & 3)*32;
    const int row0 = blockIdx.x * 128;
    const int b = blockIdx.x >> 5;
    const float* Asrc = g_pq + (size_t)row0*MM;
    const float* Bsrc = g_kvT + (size_t)b*DVV*MM;
    float acc[4][4][4] = {};
    const int dr = tid >> 1, dh = tid & 1;

    ksm[tid] = g_ksum[b*MM + tid];
    if (tid < 128) sden[tid] = 0.0f;

    { ldR4(sb, Asrc, MM, tid); ldR4(sb + TILE_B, Bsrc, MM, tid); CP_COMMIT(); }
    for (int c = 0; c < 8; c++) {
        if (c+1 < 8) {
            uint32_t st = sb + ((c+1)&1)*STG2_B;
            ldR4(st, Asrc + (c+1)*32, MM, tid);
            ldR4(st + TILE_B, Bsrc + (c+1)*32, MM, tid);
            CP_COMMIT();
            CP_WAIT1();
        } else {
            CP_WAIT0();
        }
        __syncthreads();
        const float* S = (const float*)(smarr + (c&1)*STG2_B);
        {
            float s = 0.0f;
            #pragma unroll
            for (int j = 0; j < 16; j++)
                s += S[dr*LDR + dh*16 + j] * ksm[c*32 + dh*16 + j];
            atomicAdd(&sden[dr], s);
        }
        coreR(S, S + TILE_F, acc, wm, wn, gid, tig);
        __syncthreads();
    }
    #pragma unroll
    for (int im = 0; im < 4; im++) {
        #pragma unroll
        for (int jn = 0; jn < 4; jn++) {
            int lrow = wm + im*16 + gid;
            int row = row0 + lrow;
            int col = wn + jn*8 + tig*2;
            float inv0 = 1.0f / (sden[lrow]     + EPSV);
            float inv1 = 1.0f / (sden[lrow + 8] + EPSV);
            float2 v;
            v.x = acc[im][jn][0]*inv0; v.y = acc[im][jn][1]*inv0;
            *(float2*)(out + (size_t)row*DVV + col) = v;
            v.x = acc[im][jn][2]*inv1; v.y = acc[im][jn][3]*inv1;
            *(float2*)(out + (size_t)(row+8)*DVV + col) = v;
        }
    }
}

// ---------------- launch ------------------------------------------------------
extern "C" void kernel_launch(void* const* d_in, const int* in_sizes, int n_in,
                              void* d_out, int out_size) {
    const float* x     = (const float*)d_in[0];
    const float* Wq    = (const float*)d_in[1];
    const float* bq    = (const float*)d_in[2];
    const float* Wk    = (const float*)d_in[3];
    const float* bk    = (const float*)d_in[4];
    const float* Wv    = (const float*)d_in[5];
    const float* bv    = (const float*)d_in[6];
    const float* omega = (const float*)d_in[7];
    float* out = (float*)d_out;

    cudaFuncSetAttribute(k1_all, cudaFuncAttributeMaxDynamicSharedMemorySize, SMEM_K1);
    cudaFuncSetAttribute(k2_mma, cudaFuncAttributeMaxDynamicSharedMemorySize, SMEM_K2);
    cudaFuncSetAttribute(k4_mma, cudaFuncAttributeMaxDynamicSharedMemorySize, SMEM2);
    cudaFuncSetAttribute(k5_mma, cudaFuncAttributeMaxDynamicSharedMemorySize, SMEM2);

    k_prep_w<<<1536, 256>>>(Wq, Wk, Wv);
    k_prep_om<<<128, 256>>>(omega);
    k0_init<<<64, 256>>>();
    k1_all<<<dim3(3, 256), 256, SMEM_K1>>>(x, bq, bk, bv);
    k2_mma<<<dim3(2, 2, 256), 256, SMEM_K2>>>();
    k3a<<<TT/8, 256>>>();
    k3b<<<2048, 256>>>();
    k4_mma<<<dim3(8, 2, 8), 256, SMEM2>>>();
    k4c_round<<<256, 256>>>();
    k5_mma<<<256, 256, SMEM2>>>(out);
}

// round 17
// speedup vs baseline: 1.0712x; 1.0043x over previous
#include <cuda_runtime.h>
#include <cuda_bf16.h>
#include <math.h>
#include <stdint.h>

#define BB 8
#define SS 4096
#define TT (BB*SS)          // 32768 tokens
#define DD 1024
#define DKK 128
#define DVV 128
#define MM 256
#define EPSV 1e-6f

#define LDR 36              // fp32 row-major smem leading dim (floats)
#define LDT 136             // fp32 k-major smem leading dim (floats)
#define TILE_B 18432        // fp32 128x32 tile w/ pad, bytes
#define TILE_F 4608
#define BT_B 8192           // bf16 128x32 tile, swizzled, no pad

#define K1X_STG (TILE_B + 2*BT_B)        // Xraw + Bh + Bm = 34816
#define SMEM_K1 (2*K1X_STG + 2*BT_B)     // + Ah, Am = 86016 (2 CTA/SM)
#define K2_STG (4*BT_B)
#define SMEM_K2 (2*K2_STG)  // 65536
#define STG2_B (2*TILE_B)
#define SMEM2 (2*STG2_B)    // 73728 (k4, k5)

// ---------------- scratch (device globals; no allocation allowed) -------------
__device__ __align__(128) __nv_bfloat16 g_Wbh[384*DD];   // Wq|Wk|Wv transposed [n][k], hi
__device__ __align__(128) __nv_bfloat16 g_Wbm[384*DD];   // mid
__device__ __align__(128) __nv_bfloat16 g_ombh[MM*DKK];
__device__ __align__(128) __nv_bfloat16 g_ombm[MM*DKK];
__device__ __align__(128) __nv_bfloat16 g_qbh[(size_t)TT*DKK];
__device__ __align__(128) __nv_bfloat16 g_qbm[(size_t)TT*DKK];
__device__ __align__(128) __nv_bfloat16 g_kbh[(size_t)TT*DKK];
__device__ __align__(128) __nv_bfloat16 g_kbm[(size_t)TT*DKK];
__device__ float g_vr[(size_t)TT*DVV];      // v, tf32-rounded
__device__ float g_pq[(size_t)TT*MM];       // logits, then phi_q (tf32-rounded)
__device__ float g_pk[(size_t)TT*MM];       // logits, then phi_k (tf32-rounded)
__device__ float g_qn[TT];
__device__ float g_kn[TT];
__device__ float g_kvT[BB*DVV*MM];          // kv transposed [b][d][m]
__device__ float g_ksum[BB*MM];
__device__ float g_gkmax;

// ---------------- helpers -----------------------------------------------------
__device__ __forceinline__ uint32_t smem_u32(const void* p) {
    uint32_t a;
    asm("{ .reg .u64 t; cvta.to.shared.u64 t, %1; cvt.u32.u64 %0, t; }" : "=r"(a) : "l"(p));
    return a;
}
__device__ __forceinline__ float rndtf(float x) {
    uint32_t r; asm("cvt.rna.tf32.f32 %0, %1;" : "=r"(r) : "f"(x));
    return __uint_as_float(r);
}
__device__ __forceinline__ void atomicMaxFloat(float* addr, float v) {
    if (v >= 0.0f) atomicMax((int*)addr, __float_as_int(v));
    else           atomicMin((unsigned int*)addr, __float_as_uint(v));
}
__device__ __forceinline__ void cpa16(uint32_t d, const void* s) {
    asm volatile("cp.async.cg.shared.global [%0], [%1], 16;" :: "r"(d), "l"(s));
}
#define CP_COMMIT() asm volatile("cp.async.commit_group;" ::: "memory")
#define CP_WAIT0()  asm volatile("cp.async.wait_group 0;" ::: "memory")
#define CP_WAIT1()  asm volatile("cp.async.wait_group 1;" ::: "memory")

#define MMA8(d, a, b) \
    asm volatile("mma.sync.aligned.m16n8k8.row.col.f32.tf32.tf32.f32 " \
        "{%0,%1,%2,%3}, {%4,%5,%6,%7}, {%8,%9}, {%0,%1,%2,%3};" \
        : "+f"((d)[0]), "+f"((d)[1]), "+f"((d)[2]), "+f"((d)[3]) \
        : "r"((a)[0]), "r"((a)[1]), "r"((a)[2]), "r"((a)[3]), \
          "r"((b)[0]), "r"((b)[1]))

#define MMA16(d, a, b) \
    asm volatile("mma.sync.aligned.m16n8k16.row.col.f32.bf16.bf16.f32 " \
        "{%0,%1,%2,%3}, {%4,%5,%6,%7}, {%8,%9}, {%0,%1,%2,%3};" \
        : "+f"((d)[0]), "+f"((d)[1]), "+f"((d)[2]), "+f"((d)[3]) \
        : "r"((a)[0]), "r"((a)[1]), "r"((a)[2]), "r"((a)[3]), \
          "r"((b)[0]), "r"((b)[1]))

#define LDSM4(r0, r1, r2, r3, addr) \
    asm volatile("ldmatrix.sync.aligned.m8n8.x4.shared.b16 {%0,%1,%2,%3}, [%4];" \
        : "=r"(r0), "=r"(r1), "=r"(r2), "=r"(r3) : "r"(addr))

// fp32 loaders
__device__ __forceinline__ void ldR4(uint32_t sb, const float* src, int ldg, int tid) {
    #pragma unroll
    for (int t = 0; t < 4; t++) {
        int idx = tid + t*256, r = idx >> 3, c = idx & 7;
        cpa16(sb + (uint32_t)(r*LDR + c*4)*4u, src + (size_t)r*ldg + c*4);
    }
}
__device__ __forceinline__ void ldT4(uint32_t sb, const float* src, int ldg, int tid) {
    #pragma unroll
    for (int t = 0; t < 4; t++) {
        int idx = tid + t*256, r = idx >> 5, c = idx & 31;
        cpa16(sb + (uint32_t)(r*LDT + c*4)*4u, src + (size_t)r*ldg + c*4);
    }
}
// bf16 tile loader with XOR swizzle: 128 rows x 32 bf16 (64B/row), granule^=(r>>1)&3
__device__ __forceinline__ void ldBS(uint32_t sb, const __nv_bfloat16* src, int ldg, int tid) {
    #pragma unroll
    for (int t = 0; t < 2; t++) {
        int idx = tid + t*256, r = idx >> 2, c = idx & 3;
        uint32_t cs = (uint32_t)(c ^ ((r >> 1) & 3));
        cpa16(sb + (uint32_t)(r*64) + cs*16u, src + (size_t)r*ldg + c*8);
    }
}

// fp32 tf32 mma cores (k4/k5)
__device__ __forceinline__ void coreR(const float* As, const float* Bs,
                                      float acc[4][4][4], int wm, int wn, int gid, int tig) {
    #pragma unroll
    for (int k8 = 0; k8 < 32; k8 += 8) {
        uint32_t a[4][4], b[4][2];
        #pragma unroll
        for (int im = 0; im < 4; im++) {
            int rb = wm + im*16;
            a[im][0] = __float_as_uint(As[(rb+gid  )*LDR + k8+tig  ]);
            a[im][1] = __float_as_uint(As[(rb+gid+8)*LDR + k8+tig  ]);
            a[im][2] = __float_as_uint(As[(rb+gid  )*LDR + k8+tig+4]);
            a[im][3] = __float_as_uint(As[(rb+gid+8)*LDR + k8+tig+4]);
        }
        #pragma unroll
        for (int jn = 0; jn < 4; jn++) {
            int nb = wn + jn*8;
            b[jn][0] = __float_as_uint(Bs[(nb+gid)*LDR + k8+tig  ]);
            b[jn][1] = __float_as_uint(Bs[(nb+gid)*LDR + k8+tig+4]);
        }
        #pragma unroll
        for (int im = 0; im < 4; im++)
            #pragma unroll
            for (int jn = 0; jn < 4; jn++)
                MMA8(acc[im][jn], a[im], b[jn]);
    }
}
__device__ __forceinline__ void coreT(const float* As, const float* Bs,
                                      float acc[4][4][4], int wm, int wn, int gid, int tig) {
    #pragma unroll
    for (int k8 = 0; k8 < 32; k8 += 8) {
        uint32_t a[4][4], b[4][2];
        #pragma unroll
        for (int im = 0; im < 4; im++) {
            int rb = wm + im*16;
            a[im][0] = __float_as_uint(As[(k8+tig  )*LDT + rb+gid  ]);
            a[im][1] = __float_as_uint(As[(k8+tig  )*LDT + rb+gid+8]);
            a[im][2] = __float_as_uint(As[(k8+tig+4)*LDT + rb+gid  ]);
            a[im][3] = __float_as_uint(As[(k8+tig+4)*LDT + rb+gid+8]);
        }
        #pragma unroll
        for (int jn = 0; jn < 4; jn++) {
            int nb = wn + jn*8;
            b[jn][0] = __float_as_uint(Bs[(k8+tig  )*LDT + nb+gid]);
            b[jn][1] = __float_as_uint(Bs[(k8+tig+4)*LDT + nb+gid]);
        }
        #pragma unroll
        for (int im = 0; im < 4; im++)
            #pragma unroll
            for (int jn = 0; jn < 4; jn++)
                MMA8(acc[im][jn], a[im], b[jn]);
    }
}
// 64x32 warp tile, bf16 m16n8k16 via ldmatrix; swizzled LDB=32 layout (in-loop addr)
__device__ __forceinline__ void coreRB(uint32_t As, uint32_t Bs,
                                       float acc[4][4][4], int wm, int wn, int lane) {
    const int l15 = lane & 15;
    const int ahi = (lane >> 4) & 1;
    const int l7  = lane & 7;
    const int bk  = (lane >> 3) & 1;
    const int bn  = (lane >> 4) & 1;
    #pragma unroll
    for (int k16 = 0; k16 < 32; k16 += 16) {
        uint32_t a[4][4], b[4][2];
        const int gbase = k16 >> 3;
        #pragma unroll
        for (int im = 0; im < 4; im++) {
            int r = wm + im*16 + l15;
            uint32_t g = (uint32_t)((gbase + ahi) ^ ((r >> 1) & 3));
            uint32_t addr = As + (uint32_t)(r*64) + g*16u;
            LDSM4(a[im][0], a[im][1], a[im][2], a[im][3], addr);
        }
        #pragma unroll
        for (int jp = 0; jp < 2; jp++) {
            int r = wn + jp*16 + bn*8 + l7;
            uint32_t g = (uint32_t)((gbase + bk) ^ ((r >> 1) & 3));
            uint32_t addr = Bs + (uint32_t)(r*64) + g*16u;
            uint32_t r0, r1, r2, r3;
            LDSM4(r0, r1, r2, r3, addr);
            b[jp*2  ][0] = r0; b[jp*2  ][1] = r1;
            b[jp*2+1][0] = r2; b[jp*2+1][1] = r3;
        }
        #pragma unroll
        for (int im = 0; im < 4; im++)
            #pragma unroll
            for (int jn = 0; jn < 4; jn++)
                MMA16(acc[im][jn], a[im], b[jn]);
    }
}

// split raw fp32 tile (layout R) -> bf16 hi/mid tiles (swizzled LDB=32 layout)
__device__ __forceinline__ void split_bfsw(const float* Xr, char* Ahp, char* Amp, int tid) {
    const int r = tid >> 1, c0 = (tid & 1) * 16;
    const uint32_t rb = (uint32_t)(r * 64);
    const uint32_t sw = (uint32_t)((r >> 1) & 3);
    #pragma unroll
    for (int j = 0; j < 4; j++) {
        int c = c0 + j*4;
        float4 v = *(const float4*)&Xr[r*LDR + c];
        uint32_t g = ((uint32_t)(c >> 3)) ^ sw;
        uint32_t off = rb + g*16u + (uint32_t)(c & 7)*2u;
        __nv_bfloat16 hx = __float2bfloat16_rn(v.x);
        __nv_bfloat16 hy = __float2bfloat16_rn(v.y);
        __nv_bfloat16 hz = __float2bfloat16_rn(v.z);
        __nv_bfloat16 hw = __float2bfloat16_rn(v.w);
        __nv_bfloat162 h01 = __halves2bfloat162(hx, hy);
        __nv_bfloat162 h23 = __halves2bfloat162(hz, hw);
        uint2 ho; ho.x = *(uint32_t*)&h01; ho.y = *(uint32_t*)&h23;
        *(uint2*)(Ahp + off) = ho;
        __nv_bfloat162 m01 = __halves2bfloat162(
            __float2bfloat16_rn(v.x - __bfloat162float(hx)),
            __float2bfloat16_rn(v.y - __bfloat162float(hy)));
        __nv_bfloat162 m23 = __halves2bfloat162(
            __float2bfloat16_rn(v.z - __bfloat162float(hz)),
            __float2bfloat16_rn(v.w - __bfloat162float(hw)));
        uint2 mo; mo.x = *(uint32_t*)&m01; mo.y = *(uint32_t*)&m23;
        *(uint2*)(Amp + off) = mo;
    }
}

// ---------------- prep kernels ------------------------------------------------
__global__ __launch_bounds__(256) void k_prep_w(
    const float* __restrict__ Wq, const float* __restrict__ Wk, const float* __restrict__ Wv) {
    int idx = blockIdx.x * 256 + threadIdx.x;          // 0..393215
    int row = idx >> 10, k = idx & 1023;
    const float* W = (row < 128) ? Wq : (row < 256) ? Wk : Wv;
    int n = row & 127;
    float v = W[(size_t)k * DKK + n];
    __nv_bfloat16 h = __float2bfloat16_rn(v);
    g_Wbh[idx] = h;
    g_Wbm[idx] = __float2bfloat16_rn(v - __bfloat162float(h));
}
__global__ __launch_bounds__(256) void k_prep_om(const float* __restrict__ om) {
    int idx = blockIdx.x * 256 + threadIdx.x;          // 0..32767
    float v = om[idx];
    __nv_bfloat16 h = __float2bfloat16_rn(v);
    g_ombh[idx] = h;
    g_ombm[idx] = __float2bfloat16_rn(v - __bfloat162float(h));
}
__global__ void k0_init() {
    int tid = blockIdx.x * blockDim.x + threadIdx.x;
    int nt  = gridDim.x * blockDim.x;
    if (tid == 0) g_gkmax = __int_as_float(0xff800000);
    for (int i = tid; i < BB*DVV*MM; i += nt) g_kvT[i] = 0.0f;
    for (int i = tid; i < BB*MM;     i += nt) g_ksum[i] = 0.0f;
}

// ---------------- K1: unified q/k/v GEMM, bf16x3, in-smem x split -------------
// grid (3, 256): blockIdx.x = which (L2 reuse of x across q/k/v), .y = row block
__global__ __launch_bounds__(256,2) void k1_all(
    const float* __restrict__ x,
    const float* __restrict__ bq, const float* __restrict__ bk, const float* __restrict__ bv) {
    extern __shared__ char smarr[];
    __shared__ float snrm[128];
    uint32_t sb = smem_u32(smarr);
    const int tid = threadIdx.x, lane = tid & 31, wid = tid >> 5;
    const int gid = lane >> 2, tig = lane & 3;
    const int wm = (wid >> 2)*64, wn = (wid & 3)*32;
    const int which = blockIdx.x;
    const int row0 = blockIdx.y * 128;
    const float* X = x + (size_t)row0*DD;
    const __nv_bfloat16* Wh = g_Wbh + (size_t)which*128*DD;
    const __nv_bfloat16* Wm = g_Wbm + (size_t)which*128*DD;
    const uint32_t Ah_a = sb + 2*K1X_STG;
    const uint32_t Am_a = Ah_a + BT_B;
    char* Ahp = smarr + 2*K1X_STG;
    char* Amp = Ahp + BT_B;
    float acc[4][4][4] = {};

    if (tid < 128) snrm[tid] = 0.0f;

    {   // prologue: stage 0 = Xraw(fp32), Bh, Bm
        ldR4(sb, X, DD, tid);
        ldBS(sb + TILE_B,        Wh, DD, tid);
        ldBS(sb + TILE_B + BT_B, Wm, DD, tid);
        CP_COMMIT();
    }
    for (int c = 0; c < 32; c++) {
        CP_WAIT0();
        __syncthreads();                       // stage(c) ready; compute(c-1) done
        if (c+1 < 32) {
            uint32_t st = sb + ((c+1)&1)*K1X_STG;
            const int o = (c+1)*32;
            ldR4(st, X + o, DD, tid);
            ldBS(st + TILE_B,        Wh + o, DD, tid);
            ldBS(st + TILE_B + BT_B, Wm + o, DD, tid);
            CP_COMMIT();
        }
        const uint32_t S = sb + (c&1)*K1X_STG;
        split_bfsw((const float*)(smarr + (c&1)*K1X_STG), Ahp, Amp, tid);
        __syncthreads();                       // Ah/Am ready
        coreRB(Ah_a, S + TILE_B,        acc, wm, wn, lane);       // Ah*Bh
        coreRB(Ah_a, S + TILE_B + BT_B, acc, wm, wn, lane);       // Ah*Bm
        coreRB(Am_a, S + TILE_B,        acc, wm, wn, lane);       // Am*Bh
    }
    if (which < 2) {
        const float QKS = 0.29730177875068026f;   // 128^-0.25
        const float* bias  = which ? bk : bq;
        __nv_bfloat16* oh = which ? g_kbh : g_qbh;
        __nv_bfloat16* om = which ? g_kbm : g_qbm;
        #pragma unroll
        for (int im = 0; im < 4; im++) {
            #pragma unroll
            for (int half = 0; half < 2; half++) {
                int row = row0 + wm + im*16 + gid + half*8;
                float rs = 0.0f;
                #pragma unroll
                for (int jn = 0; jn < 4; jn++) {
                    int col = wn + jn*8 + tig*2;
                    float f0 = (acc[im][jn][half*2+0] + bias[col])*QKS;
                    float f1 = (acc[im][jn][half*2+1] + bias[col+1])*QKS;
                    rs += f0*f0 + f1*f1;
                    size_t off = (size_t)row*128 + col;
                    __nv_bfloat16 h0 = __float2bfloat16_rn(f0);
                    __nv_bfloat16 h1 = __float2bfloat16_rn(f1);
                    *(__nv_bfloat162*)(oh + off) = __halves2bfloat162(h0, h1);
                    __nv_bfloat16 m0 = __float2bfloat16_rn(f0 - __bfloat162float(h0));
                    __nv_bfloat16 m1 = __float2bfloat16_rn(f1 - __bfloat162float(h1));
                    *(__nv_bfloat162*)(om + off) = __halves2bfloat162(m0, m1);
                }
                atomicAdd(&snrm[row - row0], rs);
            }
        }
        __syncthreads();
        if (tid < 128) (which ? g_kn : g_qn)[row0 + tid] = snrm[tid];
    } else {
        #pragma unroll
        for (int im = 0; im < 4; im++) {
            #pragma unroll
            for (int jn = 0; jn < 4; jn++) {
                int row = row0 + wm + im*16 + gid;
                int col = wn + jn*8 + tig*2;
                float b0 = bv[col], b1 = bv[col+1];
                float2 v;
                v.x = rndtf(acc[im][jn][0] + b0); v.y = rndtf(acc[im][jn][1] + b1);
                *(float2*)(g_vr + (size_t)row*128 + col) = v;
                v.x = rndtf(acc[im][jn][2] + b0); v.y = rndtf(acc[im][jn][3] + b1);
                *(float2*)(g_vr + (size_t)(row+8)*128 + col) = v;
            }
        }
    }
}

// ---------------- K2: feature projection, bf16x3 + ldmatrix -------------------
// grid (2, 2, 256): .x = mh, .y = isK, .z = row block
__global__ __launch_bounds__(256,2) void k2_mma() {
    extern __shared__ char smarr[];
    uint32_t sb = smem_u32(smarr);
    const int tid = threadIdx.x, lane = tid & 31, wid = tid >> 5;
    const int gid = lane >> 2, tig = lane & 3;
    const int wm = (wid >> 2)*64, wn = (wid & 3)*32;
    const int mh = blockIdx.x;
    const bool isK = blockIdx.y != 0;
    const int row0 = blockIdx.z * 128;
    const __nv_bfloat16* Ah = (isK ? g_kbh : g_qbh) + (size_t)row0*DKK;
    const __nv_bfloat16* Am = (isK ? g_kbm : g_qbm) + (size_t)row0*DKK;
    const __nv_bfloat16* Obh = g_ombh + (size_t)mh*128*DKK;
    const __nv_bfloat16* Obm = g_ombm + (size_t)mh*128*DKK;
    const float* nrm  = isK ? g_kn : g_qn;
    float* out        = isK ? g_pk : g_pq;
    float acc[4][4][4] = {};
    __shared__ float wmax[8];

    {
        ldBS(sb,          Ah, DKK, tid);
        ldBS(sb +   BT_B, Am, DKK, tid);
        ldBS(sb + 2*BT_B, Obh, DKK, tid);
        ldBS(sb + 3*BT_B, Obm, DKK, tid);
        CP_COMMIT();
    }
    for (int c = 0; c < 4; c++) {
        if (c+1 < 4) {
            uint32_t st = sb + ((c+1)&1)*K2_STG;
            const int o = (c+1)*32;
            ldBS(st,          Ah + o, DKK, tid);
            ldBS(st +   BT_B, Am + o, DKK, tid);
            ldBS(st + 2*BT_B, Obh + o, DKK, tid);
            ldBS(st + 3*BT_B, Obm + o, DKK, tid);
            CP_COMMIT();
            CP_WAIT1();
        } else {
            CP_WAIT0();
        }
        __syncthreads();
        const uint32_t S = sb + (c&1)*K2_STG;
        coreRB(S,        S + 2*BT_B, acc, wm, wn, lane);
        coreRB(S,        S + 3*BT_B, acc, wm, wn, lane);
        coreRB(S + BT_B, S + 2*BT_B, acc, wm, wn, lane);
        __syncthreads();
    }
    float lmax = __int_as_float(0xff800000);
    #pragma unroll
    for (int im = 0; im < 4; im++) {
        #pragma unroll
        for (int jn = 0; jn < 4; jn++) {
            int row = row0 + wm + im*16 + gid;
            int col = mh*128 + wn + jn*8 + tig*2;
            float hn0 = 0.5f * nrm[row], hn1 = 0.5f * nrm[row+8];
            float2 v;
            v.x = acc[im][jn][0] - hn0; v.y = acc[im][jn][1] - hn0;
            *(float2*)(out + (size_t)row*MM + col) = v;
            if (isK) lmax = fmaxf(lmax, fmaxf(v.x, v.y));
            v.x = acc[im][jn][2] - hn1; v.y = acc[im][jn][3] - hn1;
            *(float2*)(out + (size_t)(row+8)*MM + col) = v;
            if (isK) lmax = fmaxf(lmax, fmaxf(v.x, v.y));
        }
    }
    if (isK) {
        #pragma unroll
        for (int o = 16; o; o >>= 1) lmax = fmaxf(lmax, __shfl_xor_sync(0xffffffffu, lmax, o));
        if (lane == 0) wmax[wid] = lmax;
        __syncthreads();
        if (tid == 0) {
            float bm = wmax[0];
            #pragma unroll
            for (int w = 1; w < 8; w++) bm = fmaxf(bm, wmax[w]);
            atomicMaxFloat(&g_gkmax, bm);
        }
    }
}

// ---------------- K3: phi_q (rowmax+exp) AND phi_k (global exp), one pass -----
__global__ __launch_bounds__(256) void k3_fused() {
    int t = blockIdx.x * 8 + (threadIdx.x >> 5);
    int lane = threadIdx.x & 31;
    const float gm = g_gkmax;
    // phi_q: per-row max + exp in place
    {
        float* pq = g_pq + (size_t)t*MM;
        float4 v0 = *(float4*)(pq + lane*4);
        float4 v1 = *(float4*)(pq + 128 + lane*4);
        float mx = fmaxf(fmaxf(fmaxf(v0.x, v0.y), fmaxf(v0.z, v0.w)),
                         fmaxf(fmaxf(v1.x, v1.y), fmaxf(v1.z, v1.w)));
        #pragma unroll
        for (int o = 16; o; o >>= 1) mx = fmaxf(mx, __shfl_xor_sync(0xffffffffu, mx, o));
        float4 e0, e1;
        e0.x = rndtf(expf(v0.x - mx)*0.0625f); e0.y = rndtf(expf(v0.y - mx)*0.0625f);
        e0.z = rndtf(expf(v0.z - mx)*0.0625f); e0.w = rndtf(expf(v0.w - mx)*0.0625f);
        e1.x = rndtf(expf(v1.x - mx)*0.0625f); e1.y = rndtf(expf(v1.y - mx)*0.0625f);
        e1.z = rndtf(expf(v1.z - mx)*0.0625f); e1.w = rndtf(expf(v1.w - mx)*0.0625f);
        *(float4*)(pq + lane*4) = e0;
        *(float4*)(pq + 128 + lane*4) = e1;
    }
    // phi_k: global-max exp in place (same rows)
    {
        float* pk = g_pk + (size_t)t*MM;
        float4 v0 = *(float4*)(pk + lane*4);
        float4 v1 = *(float4*)(pk + 128 + lane*4);
        float4 e0, e1;
        e0.x = rndtf(expf(v0.x - gm)*0.0625f); e0.y = rndtf(expf(v0.y - gm)*0.0625f);
        e0.z = rndtf(expf(v0.z - gm)*0.0625f); e0.w = rndtf(expf(v0.w - gm)*0.0625f);
        e1.x = rndtf(expf(v1.x - gm)*0.0625f); e1.y = rndtf(expf(v1.y - gm)*0.0625f);
        e1.z = rndtf(expf(v1.z - gm)*0.0625f); e1.w = rndtf(expf(v1.w - gm)*0.0625f);
        *(float4*)(pk + lane*4) = e0;
        *(float4*)(pk + 128 + lane*4) = e1;
    }
}

// ---------------- K4: kvT += phi_k^T v  (fused ksum) --------------------------
__global__ __launch_bounds__(256,2) void k4_mma() {
    extern __shared__ char smarr[];
    uint32_t sb = smem_u32(smarr);
    const int tid = threadIdx.x, lane = tid & 31, wid = tid >> 5;
    const int gid = lane >> 2, tig = lane & 3;
    const int wm = (wid >> 2)*64, wn = (wid & 3)*32;
    const int b = blockIdx.x, m0 = blockIdx.y * 128, sp = blockIdx.z;
    const float* Asrc = g_pk + ((size_t)b*SS + sp*512)*MM + m0;
    const float* Bsrc = g_vr + ((size_t)b*SS + sp*512)*DVV;
    float acc[4][4][4] = {};
    float ks = 0.0f;
    const int km = tid & 127, kh = tid >> 7;

    { ldT4(sb, Asrc, MM, tid); ldT4(sb + TILE_B, Bsrc, DVV, tid); CP_COMMIT(); }
    for (int c = 0; c < 16; c++) {
        if (c+1 < 16) {
            uint32_t st = sb + ((c+1)&1)*STG2_B;
            ldT4(st, Asrc + (size_t)(c+1)*32*MM, MM, tid);
            ldT4(st + TILE_B, Bsrc + (size_t)(c+1)*32*DVV, DVV, tid);
            CP_COMMIT();
            CP_WAIT1();
        } else {
            CP_WAIT0();
        }
        __syncthreads();
        const float* S = (const float*)(smarr + (c&1)*STG2_B);
        coreT(S, S + TILE_F, acc, wm, wn, gid, tig);
        #pragma unroll
        for (int s = 0; s < 16; s++) ks += S[(kh*16 + s)*LDT + km];
        __syncthreads();
    }
    float* kvb = g_kvT + (size_t)b*DVV*MM;
    #pragma unroll
    for (int im = 0; im < 4; im++) {
        #pragma unroll
        for (int jn = 0; jn < 4; jn++) {
            int m = m0 + wm + im*16 + gid;
            int d = wn + jn*8 + tig*2;
            atomicAdd(&kvb[(size_t)d*MM + m],       acc[im][jn][0]);
            atomicAdd(&kvb[(size_t)(d+1)*MM + m],   acc[im][jn][1]);
            atomicAdd(&kvb[(size_t)d*MM + m+8],     acc[im][jn][2]);
            atomicAdd(&kvb[(size_t)(d+1)*MM + m+8], acc[im][jn][3]);
        }
    }
    atomicAdd(&g_ksum[b*MM + m0 + km], ks);
}

// ---------------- K4c: round kvT in place -------------------------------------
__global__ __launch_bounds__(256) void k4c_round() {
    int i = blockIdx.x * 256 + threadIdx.x;
    int n = BB*DVV*MM;
    for (; i < n; i += gridDim.x * 256) g_kvT[i] = rndtf(g_kvT[i]);
}

// ---------------- K5: out = (phi_q @ kv) / den  (fused den) -------------------
__global__ __launch_bounds__(256,2) void k5_mma(float* __restrict__ out) {
    extern __shared__ char smarr[];
    __shared__ float ksm[MM];
    __shared__ float sden[128];
    uint32_t sb = smem_u32(smarr);
    const int tid = threadIdx.x, lane = tid & 31, wid = tid >> 5;
    const int gid = lane >> 2, tig = lane & 3;
    const int wm = (wid >> 2)*64, wn = (wid & 3)*32;
    const int row0 = blockIdx.x * 128;
    const int b = blockIdx.x >> 5;
    const float* Asrc = g_pq + (size_t)row0*MM;
    const float* Bsrc = g_kvT + (size_t)b*DVV*MM;
    float acc[4][4][4] = {};
    const int dr = tid >> 1, dh = tid & 1;

    ksm[tid] = g_ksum[b*MM + tid];
    if (tid < 128) sden[tid] = 0.0f;

    { ldR4(sb, Asrc, MM, tid); ldR4(sb + TILE_B, Bsrc, MM, tid); CP_COMMIT(); }
    for (int c = 0; c < 8; c++) {
        if (c+1 < 8) {
            uint32_t st = sb + ((c+1)&1)*STG2_B;
            ldR4(st, Asrc + (c+1)*32, MM, tid);
            ldR4(st + TILE_B, Bsrc + (c+1)*32, MM, tid);
            CP_COMMIT();
            CP_WAIT1();
        } else {
            CP_WAIT0();
        }
        __syncthreads();
        const float* S = (const float*)(smarr + (c&1)*STG2_B);
        {
            float s = 0.0f;
            #pragma unroll
            for (int j = 0; j < 16; j++)
                s += S[dr*LDR + dh*16 + j] * ksm[c*32 + dh*16 + j];
            atomicAdd(&sden[dr], s);
        }
        coreR(S, S + TILE_F, acc, wm, wn, gid, tig);
        __syncthreads();
    }
    #pragma unroll
    for (int im = 0; im < 4; im++) {
        #pragma unroll
        for (int jn = 0; jn < 4; jn++) {
            int lrow = wm + im*16 + gid;
            int row = row0 + lrow;
            int col = wn + jn*8 + tig*2;
            float inv0 = 1.0f / (sden[lrow]     + EPSV);
            float inv1 = 1.0f / (sden[lrow + 8] + EPSV);
            float2 v;
            v.x = acc[im][jn][0]*inv0; v.y = acc[im][jn][1]*inv0;
            *(float2*)(out + (size_t)row*DVV + col) = v;
            v.x = acc[im][jn][2]*inv1; v.y = acc[im][jn][3]*inv1;
            *(float2*)(out + (size_t)(row+8)*DVV + col) = v;
        }
    }
}

// ---------------- launch ------------------------------------------------------
extern "C" void kernel_launch(void* const* d_in, const int* in_sizes, int n_in,
                              void* d_out, int out_size) {
    const float* x     = (const float*)d_in[0];
    const float* Wq    = (const float*)d_in[1];
    const float* bq    = (const float*)d_in[2];
    const float* Wk    = (const float*)d_in[3];
    const float* bk    = (const float*)d_in[4];
    const float* Wv    = (const float*)d_in[5];
    const float* bv    = (const float*)d_in[6];
    const float* omega = (const float*)d_in[7];
    float* out = (float*)d_out;

    cudaFuncSetAttribute(k1_all, cudaFuncAttributeMaxDynamicSharedMemorySize, SMEM_K1);
    cudaFuncSetAttribute(k2_mma, cudaFuncAttributeMaxDynamicSharedMemorySize, SMEM_K2);
    cudaFuncSetAttribute(k4_mma, cudaFuncAttributeMaxDynamicSharedMemorySize, SMEM2);
    cudaFuncSetAttribute(k5_mma, cudaFuncAttributeMaxDynamicSharedMemorySize, SMEM2);

    k_prep_w<<<1536, 256>>>(Wq, Wk, Wv);
    k_prep_om<<<128, 256>>>(omega);
    k0_init<<<64, 256>>>();
    k1_all<<<dim3(3, 256), 256, SMEM_K1>>>(x, bq, bk, bv);
    k2_mma<<<dim3(2, 2, 256), 256, SMEM_K2>>>();
    k3_fused<<<TT/8, 256>>>();
    k4_mma<<<dim3(8, 2, 8), 256, SMEM2>>>();
    k4c_round<<<256, 256>>>();
    k5_mma<<<256, 256, SMEM2>>>(out);
}